// round 1
// baseline (speedup 1.0000x reference)
#include <cuda_runtime.h>
#include <cstdint>

// ---------------------------------------------------------------------------
// NeRF fused forward. One block = 64 points, 256 threads, fully fused MLP.
// Activations in SMEM transposed [k][m] (stride SA=64). Weights streamed from
// L2 into SMEM via cp.async, double-buffered KC=32-row chunks.
// FP32 math throughout via packed fma.rn.f32x2 (2 MAC/instr).
// ---------------------------------------------------------------------------

namespace {

constexpr int TM       = 64;    // points per block
constexpr int NTHREADS = 256;
constexpr int KC       = 32;    // weight K-chunk rows
constexpr int SA       = 64;    // activation m-stride (floats)

// SMEM layout (float offsets)
constexpr int OFF_A0  = 0;
constexpr int OFF_A1  = OFF_A0  + 256 * SA;   // 16384
constexpr int OFF_PEX = OFF_A1  + 256 * SA;   // 32768
constexpr int OFF_PED = OFF_PEX + 64 * SA;    // 36864
constexpr int OFF_WB  = OFF_PED + 40 * SA;    // 39424
constexpr int SMEM_FLOATS = OFF_WB + 2 * KC * 256;  // 55808
constexpr int SMEM_BYTES  = SMEM_FLOATS * 4;        // 223232 < 232448 limit

__device__ __forceinline__ unsigned long long ffma2(unsigned long long a,
                                                    unsigned long long b,
                                                    unsigned long long c) {
    unsigned long long d;
    asm("fma.rn.f32x2 %0, %1, %2, %3;" : "=l"(d) : "l"(a), "l"(b), "l"(c));
    return d;
}
__device__ __forceinline__ unsigned long long pack2(float lo, float hi) {
    unsigned long long d;
    asm("mov.b64 %0, {%1, %2};" : "=l"(d) : "f"(lo), "f"(hi));
    return d;
}
__device__ __forceinline__ void unpack2(unsigned long long v, float& lo, float& hi) {
    asm("mov.b64 {%0, %1}, %2;" : "=f"(lo), "=f"(hi) : "l"(v));
}
__device__ __forceinline__ void cp_async16(uint32_t saddr, const void* gaddr) {
    asm volatile("cp.async.cg.shared.global [%0], [%1], 16;" :: "r"(saddr), "l"(gaddr));
}
__device__ __forceinline__ void cp_commit() {
    asm volatile("cp.async.commit_group;" ::: "memory");
}
template <int n> __device__ __forceinline__ void cp_wait() {
    asm volatile("cp.async.wait_group %0;" :: "n"(n) : "memory");
}

// Accurate sin/cos: double range reduction, then device sinf/cosf on |r|<=pi.
__device__ __forceinline__ void sincos_red(float a, float& s, float& c) {
    double ad = (double)a;
    double k  = rint(ad * 0.15915494309189535);           // 1/(2*pi)
    float rf  = (float)fma(k, -6.283185307179586, ad);    // a - k*2pi
    s = sinf(rf);
    c = cosf(rf);
}

struct KParams {
    const float* x;
    const float* dir;
    const float* g1W[5]; const float* g1b[5];
    const float* g2W[3]; const float* g2b[3];
    const float* c0W;  const float* c0b;
    const float* c1W;  const float* c1b;
    const float* sigW; const float* sigb;
    float* out;
};

// One linear layer: dest[n][m] = act( sum_k A[k][m]*W[k][n] + bias[n] ).
// Input may be a concat of two activation tensors (A_a rows [0,K_a), A_b rows
// [K_a, K_a+K_b)); W holds all K_a+K_b rows contiguously.
__device__ void run_layer(float* smem, int tid,
                          const float* A_a, int K_a,
                          const float* A_b, int K_b,
                          const float* W, const float* bias,
                          float* dest, bool relu)
{
    const int ni = tid & 15;
    const int mi = tid >> 4;
    const int m0 = mi << 2;     // 4 m per thread
    const int n0 = ni << 1;     // n pairs: {32j + 2ni, +1}

    float* WB = smem + OFF_WB;
    const uint32_t wb_s = (uint32_t)__cvta_generic_to_shared(WB);

    unsigned long long acc[4][8];
#pragma unroll
    for (int j = 0; j < 8; ++j) {
        unsigned long long b2 = *(const unsigned long long*)(bias + j * 32 + n0);
        acc[0][j] = b2; acc[1][j] = b2; acc[2][j] = b2; acc[3][j] = b2;
    }

#pragma unroll 1
    for (int p = 0; p < 2; ++p) {
        const float* A     = (p == 0) ? A_a : A_b;
        const int    K     = (p == 0) ? K_a : K_b;
        const int    rowOff= (p == 0) ? 0   : K_a;
        if (K == 0) continue;
        const float* Wp = W + (size_t)rowOff * 256;
        const int nch = (K + KC - 1) / KC;

        // stage chunk 0 into buf 0
        {
#pragma unroll
            for (int i = 0; i < 8; ++i) {
                int idx4 = i * NTHREADS + tid;     // 16B-unit index in chunk
                int fidx = idx4 * 4;               // float index in W part
                if (fidx < K * 256)
                    cp_async16(wb_s + (uint32_t)(idx4 * 4) * 4u, Wp + fidx);
            }
            cp_commit();
        }

#pragma unroll 1
        for (int c = 0; c < nch; ++c) {
            if (c + 1 < nch) {
                const int buf = (c + 1) & 1;
                const int cs  = (c + 1) * KC;
#pragma unroll
                for (int i = 0; i < 8; ++i) {
                    int idx4 = i * NTHREADS + tid;
                    int fidx = cs * 256 + idx4 * 4;
                    if (fidx < K * 256)
                        cp_async16(wb_s + (uint32_t)(buf * (KC * 256) + idx4 * 4) * 4u,
                                   Wp + fidx);
                }
                cp_commit();
                cp_wait<1>();     // current chunk's copies done
            } else {
                cp_wait<0>();
            }
            __syncthreads();

            const int cs  = c * KC;
            const int rem = K - cs;
            const int cnt = rem < KC ? rem : KC;
            const float* WBb  = WB + (c & 1) * (KC * 256);
            const float* Arow = A + cs * SA + m0;

#pragma unroll 2
            for (int kk = 0; kk < cnt; ++kk) {
                float4 a4 = *(const float4*)(Arow + kk * SA);
                unsigned long long a0v = pack2(a4.x, a4.x);
                unsigned long long a1v = pack2(a4.y, a4.y);
                unsigned long long a2v = pack2(a4.z, a4.z);
                unsigned long long a3v = pack2(a4.w, a4.w);
                const float* wr = WBb + kk * 256 + n0;
#pragma unroll
                for (int j = 0; j < 8; ++j) {
                    unsigned long long w2 = *(const unsigned long long*)(wr + j * 32);
                    acc[0][j] = ffma2(a0v, w2, acc[0][j]);
                    acc[1][j] = ffma2(a1v, w2, acc[1][j]);
                    acc[2][j] = ffma2(a2v, w2, acc[2][j]);
                    acc[3][j] = ffma2(a3v, w2, acc[3][j]);
                }
            }
            __syncthreads();
        }
    }

    // epilogue: activation + transposed store [n][m]
#pragma unroll
    for (int j = 0; j < 8; ++j) {
        const int n = j * 32 + n0;
#pragma unroll
        for (int m = 0; m < 4; ++m) {
            float lo, hi;
            unpack2(acc[m][j], lo, hi);
            if (relu) { lo = fmaxf(lo, 0.f); hi = fmaxf(hi, 0.f); }
            dest[n * SA + m0 + m]       = lo;
            dest[(n + 1) * SA + m0 + m] = hi;
        }
    }
    __syncthreads();
}

__global__ __launch_bounds__(NTHREADS, 1)
void nerf_kernel(KParams p)
{
    extern __shared__ float smem[];
    const int tid = threadIdx.x;
    float* A0  = smem + OFF_A0;
    float* A1  = smem + OFF_A1;
    float* PEX = smem + OFF_PEX;
    float* PED = smem + OFF_PED;

    // ---- positional encoding: [x, sin(2^l x_c), cos(2^l x_c), ...] ----
    // feature index: 0..2 = x ; 3 + 6l + t*3 + c  (t: 0=sin, 1=cos)
    if (tid < 192) {
        const int m    = tid & 63;
        const int comp = tid >> 6;           // 0..2
        const int gm   = blockIdx.x * TM + m;
        const float xv = p.x[gm * 3 + comp];
        const float dv = p.dir[gm * 3 + comp];
        PEX[comp * SA + m] = xv;
        PED[comp * SA + m] = dv;
        float f = 1.f;
#pragma unroll
        for (int l = 0; l < 10; ++l) {
            float s, c;
            sincos_red(xv * f, s, c);
            PEX[(3 + 6 * l + comp) * SA + m]     = s;
            PEX[(3 + 6 * l + 3 + comp) * SA + m] = c;
            if (l < 6) {
                sincos_red(dv * f, s, c);
                PED[(3 + 6 * l + comp) * SA + m]     = s;
                PED[(3 + 6 * l + 3 + comp) * SA + m] = c;
            }
            f *= 2.f;
        }
    }
    __syncthreads();

    // ---- MLP chain ----
    run_layer(smem, tid, PEX, 63, nullptr, 0,   p.g1W[0], p.g1b[0], A0, true);
    run_layer(smem, tid, A0, 256, nullptr, 0,   p.g1W[1], p.g1b[1], A1, true);
    run_layer(smem, tid, A1, 256, nullptr, 0,   p.g1W[2], p.g1b[2], A0, true);
    run_layer(smem, tid, A0, 256, nullptr, 0,   p.g1W[3], p.g1b[3], A1, true);
    run_layer(smem, tid, A1, 256, nullptr, 0,   p.g1W[4], p.g1b[4], A0, false); // features1 -> A0
    run_layer(smem, tid, PEX, 63, A0, 256,      p.g2W[0], p.g2b[0], A1, true);
    run_layer(smem, tid, A1, 256, nullptr, 0,   p.g2W[1], p.g2b[1], A0, true);
    run_layer(smem, tid, A0, 256, nullptr, 0,   p.g2W[2], p.g2b[2], A1, false); // features2 -> A1
    run_layer(smem, tid, PED, 39, A1, 256,      p.c0W,    p.c0b,    A0, true);  // c hidden -> A0

    // ---- heads: rgb = A0 @ c1W[256x3] + c1b ; sigma = A1 @ sigW[256] + sigb
    {
        const int m = tid & 63;
        const int q = tid >> 6;           // k-quarter
        float r = 0.f, g = 0.f, b = 0.f, s = 0.f;
        const int k0 = q * 64;
        for (int k = k0; k < k0 + 64; ++k) {
            const float h  = A0[k * SA + m];
            const float f2 = A1[k * SA + m];
            r = fmaf(h,  __ldg(p.c1W + k * 3 + 0), r);
            g = fmaf(h,  __ldg(p.c1W + k * 3 + 1), g);
            b = fmaf(h,  __ldg(p.c1W + k * 3 + 2), b);
            s = fmaf(f2, __ldg(p.sigW + k),        s);
        }
        float4* scratch = (float4*)(smem + OFF_WB);   // WB free here
        scratch[q * 64 + m] = make_float4(r, g, b, s);
        __syncthreads();
        if (tid < 64) {
            float4 t0 = scratch[tid];
            float4 t1 = scratch[64 + tid];
            float4 t2 = scratch[128 + tid];
            float4 t3 = scratch[192 + tid];
            float4 o;
            o.x = t0.x + t1.x + t2.x + t3.x + __ldg(p.c1b + 0);
            o.y = t0.y + t1.y + t2.y + t3.y + __ldg(p.c1b + 1);
            o.z = t0.z + t1.z + t2.z + t3.z + __ldg(p.c1b + 2);
            o.w = t0.w + t1.w + t2.w + t3.w + __ldg(p.sigb);
            ((float4*)p.out)[blockIdx.x * TM + tid] = o;
        }
    }
}

} // namespace

extern "C" void kernel_launch(void* const* d_in, const int* in_sizes, int n_in,
                              void* d_out, int out_size)
{
    KParams p;
    p.x   = (const float*)d_in[0];
    p.dir = (const float*)d_in[1];
    for (int i = 0; i < 5; ++i) {
        p.g1W[i] = (const float*)d_in[2 + 2 * i];
        p.g1b[i] = (const float*)d_in[3 + 2 * i];
    }
    for (int i = 0; i < 3; ++i) {
        p.g2W[i] = (const float*)d_in[12 + 2 * i];
        p.g2b[i] = (const float*)d_in[13 + 2 * i];
    }
    p.c0W  = (const float*)d_in[18]; p.c0b  = (const float*)d_in[19];
    p.c1W  = (const float*)d_in[20]; p.c1b  = (const float*)d_in[21];
    p.sigW = (const float*)d_in[22]; p.sigb = (const float*)d_in[23];
    p.out  = (float*)d_out;

    cudaFuncSetAttribute(nerf_kernel, cudaFuncAttributeMaxDynamicSharedMemorySize,
                         SMEM_BYTES);

    const int npts = in_sizes[0] / 3;
    nerf_kernel<<<npts / TM, NTHREADS, SMEM_BYTES>>>(p);
}